// round 15
// baseline (speedup 1.0000x reference)
#include <cuda_runtime.h>
#include <cuda_fp16.h>
#include <math.h>
#include <stdint.h>

// ---------------- problem constants ----------------
#define S 4096
#define HID 128
#define NHEADS 4
#define NCOE 50
#define NSCALES 4
#define NKC 4              // split-K chunks for attention
#define CHUNK (S / NKC)    // 1024 keys per chunk
#define QT 128             // queries per block (8 warps x 16)
#define KT 64              // key tile
#define NT_CH (CHUNK / KT) // 16 tiles per chunk
#define HD 32

// KV tile image geometry (halves). Padded rows for conflict-free LDS/LDSM.
#define KROW 40                      // per-key: 32 hi + 8 pad (pad never read)
#define KIMG (KT * KROW)             // 2560 halves
#define VROW 72                      // per-dim: 64 keys + 8 pad
#define VIMG (40 * VROW)             // rows 0..31 = V, 32 = ones, 33..39 = zero
#define TILE_H (KIMG + VIMG)         // 5440 halves = 10880 B
#define TILE_U4 (TILE_H / 8)         // 680 uint4
#define NIMG (NHEADS * (S / KT))     // 256 images
#define ONES_LO ((KIMG + 32 * VROW) / 8)
#define ONES_HI (ONES_LO + KT / 8)

// log2(e)/sqrt(32): scores come out of QK in log2 domain
#define QSCALE 0.2550458572864341f

// ---------------- scratch (__device__ globals; no allocs allowed) ----------------
__device__ float  g_eig [S * HID];
__device__ float  g_qkv [S * 3 * HID];   // only Q region (cols 0..127) used
__device__ __align__(16) __half g_kv[NIMG * TILE_H];  // pre-swizzled K/V tiles
__device__ __align__(16) uint4  g_wf[6 * 4096];   // 6 weight images, fragment-ordered
__device__ float  g_pl  [NHEADS * NKC * S];        // partial sum (fixed-ref softmax)
__device__ float  g_po  [NHEADS * NKC * S * HD];   // partial (unnormalized) out
__device__ double g_xsum[HID];
__device__ float  g_coef[128];   // [0:50) scaling, [50:100) wavelet, [100:104) scales

// ---------------- mma / async helpers ----------------
__device__ __forceinline__ void mma16816(float& c0, float& c1, float& c2, float& c3,
                                         uint32_t a0, uint32_t a1, uint32_t a2, uint32_t a3,
                                         uint32_t b0, uint32_t b1) {
    asm volatile("mma.sync.aligned.m16n8k16.row.col.f32.f16.f16.f32 "
                 "{%0,%1,%2,%3}, {%4,%5,%6,%7}, {%8,%9}, {%0,%1,%2,%3};\n"
                 : "+f"(c0), "+f"(c1), "+f"(c2), "+f"(c3)
                 : "r"(a0), "r"(a1), "r"(a2), "r"(a3), "r"(b0), "r"(b1));
}

__device__ __forceinline__ void ldm_x4(uint32_t& d0, uint32_t& d1, uint32_t& d2, uint32_t& d3,
                                       uint32_t addr) {
    asm volatile("ldmatrix.sync.aligned.m8n8.x4.shared.b16 {%0,%1,%2,%3}, [%4];\n"
                 : "=r"(d0), "=r"(d1), "=r"(d2), "=r"(d3) : "r"(addr));
}

__device__ __forceinline__ void cp16(uint32_t dst, const void* src) {
    asm volatile("cp.async.cg.shared.global [%0], [%1], 16;\n" :: "r"(dst), "l"(src));
}
__device__ __forceinline__ void cp_commit() {
    asm volatile("cp.async.commit_group;\n");
}
__device__ __forceinline__ void cp_wait_all() {
    asm volatile("cp.async.wait_group 0;\n");
}

__device__ __forceinline__ uint32_t packh2(__half a, __half b) {
    __half2 t = __halves2half2(a, b);     // a -> low half
    return *reinterpret_cast<uint32_t*>(&t);
}

// split x into hi (fp16) and lo (fp16 of remainder)
__device__ __forceinline__ void hsplit(float x, __half& h, __half& l) {
    h = __float2half_rn(x);
    l = __float2half_rn(x - __half2float(h));
}

__device__ __forceinline__ uint32_t pack2f(float x, float y) {
    __half2 t = __floats2half2_rn(x, y);  // x -> low
    return *reinterpret_cast<uint32_t*>(&t);
}

// 2^a, 2^b as packed fp16x2, clamped at 14.0 (2^14 < fp16 max). -inf -> 0.
__device__ __forceinline__ uint32_t exp2h2c(float a, float b) {
    uint32_t p = pack2f(a, b);
    uint32_t c, r;
    asm("min.f16x2 %0, %1, %2;" : "=r"(c) : "r"(p), "r"(0x4B004B00u));  // 14.0|14.0
    asm("ex2.approx.f16x2 %0, %1;" : "=r"(r) : "r"(c));
    return r;
}

// ============================================================================
// W-prep: fragment-ordered fp16 hi/lo images for all 6 [128,128] weights.
// Also zeroes g_xsum and initializes g_kv static content (zeros + ones rows).
// grid = (16, 6), 256 threads.
// ============================================================================
__global__ void __launch_bounds__(256) k_wprep(const float* __restrict__ inW,
                                               const float* __restrict__ outW,
                                               const float* __restrict__ f1W,
                                               const float* __restrict__ f2W) {
    const int tid  = threadIdx.x;
    if (blockIdx.x == 0 && blockIdx.y == 0 && tid < HID) g_xsum[tid] = 0.0;

    // ---- initialize g_kv static image content (ones rows; zero pad rows) ----
    {
        const int gthread = (blockIdx.y * 16 + blockIdx.x) * 256 + tid;   // 0..24575
        const uint4 zero4 = make_uint4(0, 0, 0, 0);
        const uint4 ones4 = make_uint4(0x3C003C00u, 0x3C003C00u, 0x3C003C00u, 0x3C003C00u);
        uint4* kvp = reinterpret_cast<uint4*>(g_kv);
        for (int i = gthread; i < NIMG * TILE_U4; i += 96 * 256) {
            int s = i % TILE_U4;
            if (s >= ONES_LO) kvp[i] = (s < ONES_HI) ? ones4 : zero4;
            else if (s >= KIMG / 8 + 32 * (VROW / 8)) kvp[i] = zero4;
        }
    }

    const int lane = tid & 31;
    const int g    = lane >> 2;
    const int t4   = lane & 3;
    const int wid  = blockIdx.x * 8 + (tid >> 5);   // fragment id 0..127
    const int nt   = wid >> 3;
    const int ks   = wid & 7;

    const float* W; int ldw, c0;
    switch (blockIdx.y) {
        case 0:  W = inW;  ldw = 384; c0 = 0;   break;
        case 1:  W = inW;  ldw = 384; c0 = 128; break;
        case 2:  W = inW;  ldw = 384; c0 = 256; break;
        case 3:  W = outW; ldw = 128; c0 = 0;   break;
        case 4:  W = f1W;  ldw = 128; c0 = 0;   break;
        default: W = f2W;  ldw = 128; c0 = 0;   break;
    }

    const int n  = nt * 8 + g;
    const int k0 = ks * 16 + 2 * t4;
    float w00 = W[(k0    ) * ldw + c0 + n];
    float w01 = W[(k0 + 1) * ldw + c0 + n];
    float w80 = W[(k0 + 8) * ldw + c0 + n];
    float w81 = W[(k0 + 9) * ldw + c0 + n];
    __half h00, l00, h01, l01, h80, l80, h81, l81;
    hsplit(w00, h00, l00);  hsplit(w01, h01, l01);
    hsplit(w80, h80, l80);  hsplit(w81, h81, l81);
    uint4 f;
    f.x = packh2(h00, h01);
    f.y = packh2(h80, h81);
    f.z = packh2(l00, l01);
    f.w = packh2(l80, l81);
    g_wf[blockIdx.y * 4096 + wid * 32 + lane] = f;
}

// ============================================================================
// 2-term MMA helper: acc += Ah(32x128 smem tile, row stride 136) @ Wimg
// warp w: m-tile (w&1), n-chunk (w>>1); returns acc[4][4]
// ============================================================================
__device__ __forceinline__ void gemm_tile(const __half* __restrict__ Ahi,
                                          const uint4* __restrict__ img_p,
                                          int warp, int lane, float acc[4][4]) {
    const int g = lane >> 2, t4 = lane & 3;
    const int mt = warp & 1, ch = warp >> 1;
    const __half* ahb = &Ahi[(mt * 16 + g) * 136];
#pragma unroll
    for (int ks = 0; ks < 8; ks++) {
        const int co = ks * 16 + 2 * t4;
        uint32_t ah0 = *reinterpret_cast<const uint32_t*>(&ahb[co]);
        uint32_t ah1 = *reinterpret_cast<const uint32_t*>(&ahb[8 * 136 + co]);
        uint32_t ah2 = *reinterpret_cast<const uint32_t*>(&ahb[co + 8]);
        uint32_t ah3 = *reinterpret_cast<const uint32_t*>(&ahb[8 * 136 + co + 8]);
#pragma unroll
        for (int nt = 0; nt < 4; nt++) {
            uint4 f = img_p[((4 * ch + nt) * 8 + ks) * 32 + lane];
            mma16816(acc[nt][0], acc[nt][1], acc[nt][2], acc[nt][3],
                     ah0, ah1, ah2, ah3, f.x, f.y);
            mma16816(acc[nt][0], acc[nt][1], acc[nt][2], acc[nt][3],
                     ah0, ah1, ah2, ah3, f.z, f.w);
        }
    }
}

// ============================================================================
// qkv GEMM: Q -> float g_qkv; K/V -> fp16 g_kv images (KVOUT).
// grid = (128, 3), 256 threads. LN fused in staging.
// ============================================================================
__global__ void __launch_bounds__(256) k_qkv_mma(const float* __restrict__ A,
                                                 const float* __restrict__ bias,
                                                 float* __restrict__ C,
                                                 const float* __restrict__ lng,
                                                 const float* __restrict__ lnb) {
    __shared__ __align__(16) __half Ahi[32 * 136];
    const int tid = threadIdx.x;
    const int m0  = blockIdx.x * 32;
    const int c0  = blockIdx.y * 128;

    // ---- stage LN(A) tile, fp16 hi ----
    {
        const int r = tid >> 3, l8 = tid & 7;
        float x[16];
        const float4* ap = reinterpret_cast<const float4*>(A + (m0 + r) * HID + l8 * 16);
#pragma unroll
        for (int j = 0; j < 4; j++) {
            float4 v = ap[j];
            x[j * 4 + 0] = v.x; x[j * 4 + 1] = v.y;
            x[j * 4 + 2] = v.z; x[j * 4 + 3] = v.w;
        }
        float s = 0.0f, s2 = 0.0f;
#pragma unroll
        for (int j = 0; j < 16; j++) { s += x[j]; s2 += x[j] * x[j]; }
#pragma unroll
        for (int o = 4; o; o >>= 1) {
            s  += __shfl_xor_sync(0xffffffffu, s,  o);
            s2 += __shfl_xor_sync(0xffffffffu, s2, o);
        }
        float mean = s * (1.0f / HID);
        float rstd = rsqrtf(s2 * (1.0f / HID) - mean * mean + 1e-5f);
        uint32_t phi[8];
#pragma unroll
        for (int j = 0; j < 8; j++) {
            int cA = l8 * 16 + 2 * j, cB = cA + 1;
            float xa = (x[2 * j]     - mean) * rstd * lng[cA] + lnb[cA];
            float xb = (x[2 * j + 1] - mean) * rstd * lng[cB] + lnb[cB];
            phi[j] = pack2f(xa, xb);
        }
        uint4* dhi = reinterpret_cast<uint4*>(&Ahi[r * 136 + l8 * 16]);
        dhi[0] = make_uint4(phi[0], phi[1], phi[2], phi[3]);
        dhi[1] = make_uint4(phi[4], phi[5], phi[6], phi[7]);
    }
    __syncthreads();

    const int warp = tid >> 5, lane = tid & 31;
    float acc[4][4];
#pragma unroll
    for (int nt = 0; nt < 4; nt++)
#pragma unroll
        for (int i = 0; i < 4; i++) acc[nt][i] = 0.0f;
    gemm_tile(Ahi, &g_wf[(size_t)blockIdx.y * 4096], warp, lane, acc);

    const int g = lane >> 2, t4 = lane & 3;
    const int mt = warp & 1, ch = warp >> 1;
#pragma unroll
    for (int nt = 0; nt < 4; nt++) {
        const int ncol = c0 + (4 * ch + nt) * 8 + 2 * t4;
        const int row0 = m0 + mt * 16 + g, row1 = row0 + 8;
        float b0 = bias[ncol], b1 = bias[ncol + 1];
        float v00 = acc[nt][0] + b0, v01 = acc[nt][1] + b1;
        float v10 = acc[nt][2] + b0, v11 = acc[nt][3] + b1;
        if (blockIdx.y == 0) {
            C[row0 * 384 + ncol]     = v00;
            C[row0 * 384 + ncol + 1] = v01;
            C[row1 * 384 + ncol]     = v10;
            C[row1 * 384 + ncol + 1] = v11;
        } else {
            const int lc   = ncol - c0;
            const int head = lc >> 5, d = lc & 31;
            const size_t base = (size_t)(head * (S / KT) + (row0 >> 6)) * TILE_H;
            const int key0 = row0 & 63, key1 = row1 & 63;
            if (blockIdx.y == 1) {
                *reinterpret_cast<__half2*>(&g_kv[base + key0 * KROW + d]) =
                    __floats2half2_rn(v00, v01);
                *reinterpret_cast<__half2*>(&g_kv[base + key1 * KROW + d]) =
                    __floats2half2_rn(v10, v11);
            } else {
                g_kv[base + KIMG + d * VROW + key0]       = __float2half_rn(v00);
                g_kv[base + KIMG + (d + 1) * VROW + key0] = __float2half_rn(v01);
                g_kv[base + KIMG + d * VROW + key1]       = __float2half_rn(v10);
                g_kv[base + KIMG + (d + 1) * VROW + key1] = __float2half_rn(v11);
            }
        }
    }
}

// ============================================================================
// Fused post-attention chain, all row-local per 32-row block:
// combine(partials) -> @outW (+eig resid) -> LN -> @ffn1W + gelu -> @ffn2W
// (+eig resid) -> masked column sums into g_xsum.
// grid = 128, 256 threads.
// ============================================================================
__global__ void __launch_bounds__(256) k_ffn_fused(const float* __restrict__ outb,
                                                   const float* __restrict__ f1b,
                                                   const float* __restrict__ f2b,
                                                   const float* __restrict__ lng,
                                                   const float* __restrict__ lnb,
                                                   const int* __restrict__ snp) {
    __shared__ __align__(16) __half Ahi[32 * 136];
    __shared__ float eigS[32 * 132];
    __shared__ float colsum[128];
    const int tid = threadIdx.x;
    const int m0  = blockIdx.x * 32;
    const int warp = tid >> 5, lane = tid & 31;
    const int g = lane >> 2, t4 = lane & 3;
    const int mt = warp & 1, ch = warp >> 1;

    // ---- load eig rows into smem (residual source / running state) ----
    for (int i = tid; i < 32 * 32; i += 256) {
        int r = i >> 5, c4 = i & 31;
        float4 v = *reinterpret_cast<const float4*>(&g_eig[(m0 + r) * HID + c4 * 4]);
        *reinterpret_cast<float4*>(&eigS[r * 132 + c4 * 4]) = v;
    }
    if (tid < 128) colsum[tid] = 0.0f;

    // ---- stage attention combine (fixed-ref: plain sums) ----
    {
        const int r = tid >> 3, l8 = tid & 7;
        const int row    = m0 + r;
        const int head   = l8 >> 1;
        const int hd_off = (l8 & 1) * 16;
        float x[16];
#pragma unroll
        for (int j = 0; j < 16; j++) x[j] = 0.0f;
        float L = 0.0f;
#pragma unroll
        for (int kc = 0; kc < NKC; kc++) {
            const int p = (head * NKC + kc) * S + row;
            L += g_pl[p];
            const float4* po = reinterpret_cast<const float4*>(&g_po[(size_t)p * HD + hd_off]);
#pragma unroll
            for (int jj = 0; jj < 4; jj++) {
                float4 v = po[jj];
                x[jj * 4 + 0] += v.x;
                x[jj * 4 + 1] += v.y;
                x[jj * 4 + 2] += v.z;
                x[jj * 4 + 3] += v.w;
            }
        }
        float inv = (L > 0.0f) ? 1.0f / L : 0.0f;
        uint32_t phi[8];
#pragma unroll
        for (int j = 0; j < 8; j++)
            phi[j] = pack2f(x[2 * j] * inv, x[2 * j + 1] * inv);
        uint4* dhi = reinterpret_cast<uint4*>(&Ahi[r * 136 + l8 * 16]);
        dhi[0] = make_uint4(phi[0], phi[1], phi[2], phi[3]);
        dhi[1] = make_uint4(phi[4], phi[5], phi[6], phi[7]);
    }
    __syncthreads();

    // ---- phase A: out-proj; eig += att @ outW + b ----
    {
        float acc[4][4];
#pragma unroll
        for (int nt = 0; nt < 4; nt++)
#pragma unroll
            for (int i = 0; i < 4; i++) acc[nt][i] = 0.0f;
        gemm_tile(Ahi, &g_wf[3 * 4096], warp, lane, acc);
#pragma unroll
        for (int nt = 0; nt < 4; nt++) {
            const int ncol = (4 * ch + nt) * 8 + 2 * t4;
            const int r0 = mt * 16 + g, r1 = r0 + 8;
            float b0 = outb[ncol], b1 = outb[ncol + 1];
            eigS[r0 * 132 + ncol]     += acc[nt][0] + b0;
            eigS[r0 * 132 + ncol + 1] += acc[nt][1] + b1;
            eigS[r1 * 132 + ncol]     += acc[nt][2] + b0;
            eigS[r1 * 132 + ncol + 1] += acc[nt][3] + b1;
        }
    }
    __syncthreads();

    // ---- stage LN(eigS) -> Ahi ----
    {
        const int r = tid >> 3, l8 = tid & 7;
        float x[16];
#pragma unroll
        for (int j = 0; j < 16; j++) x[j] = eigS[r * 132 + l8 * 16 + j];
        float s = 0.0f, s2 = 0.0f;
#pragma unroll
        for (int j = 0; j < 16; j++) { s += x[j]; s2 += x[j] * x[j]; }
#pragma unroll
        for (int o = 4; o; o >>= 1) {
            s  += __shfl_xor_sync(0xffffffffu, s,  o);
            s2 += __shfl_xor_sync(0xffffffffu, s2, o);
        }
        float mean = s * (1.0f / HID);
        float rstd = rsqrtf(s2 * (1.0f / HID) - mean * mean + 1e-5f);
        uint32_t phi[8];
#pragma unroll
        for (int j = 0; j < 8; j++) {
            int cA = l8 * 16 + 2 * j, cB = cA + 1;
            float xa = (x[2 * j]     - mean) * rstd * lng[cA] + lnb[cA];
            float xb = (x[2 * j + 1] - mean) * rstd * lng[cB] + lnb[cB];
            phi[j] = pack2f(xa, xb);
        }
        uint4* dhi = reinterpret_cast<uint4*>(&Ahi[r * 136 + l8 * 16]);
        dhi[0] = make_uint4(phi[0], phi[1], phi[2], phi[3]);
        dhi[1] = make_uint4(phi[4], phi[5], phi[6], phi[7]);
    }
    __syncthreads();

    // ---- phase B: h1 = gelu(LN @ ffn1W + b); restage into Ahi ----
    {
        float acc[4][4];
#pragma unroll
        for (int nt = 0; nt < 4; nt++)
#pragma unroll
            for (int i = 0; i < 4; i++) acc[nt][i] = 0.0f;
        gemm_tile(Ahi, &g_wf[4 * 4096], warp, lane, acc);
        __syncthreads();   // all reads of Ahi done before overwrite
        const float kg = 0.70710678118654752f;
#pragma unroll
        for (int nt = 0; nt < 4; nt++) {
            const int ncol = (4 * ch + nt) * 8 + 2 * t4;
            const int r0 = mt * 16 + g, r1 = r0 + 8;
            float b0 = f1b[ncol], b1 = f1b[ncol + 1];
            float v00 = acc[nt][0] + b0, v01 = acc[nt][1] + b1;
            float v10 = acc[nt][2] + b0, v11 = acc[nt][3] + b1;
            v00 = 0.5f * v00 * (1.0f + erff(v00 * kg));
            v01 = 0.5f * v01 * (1.0f + erff(v01 * kg));
            v10 = 0.5f * v10 * (1.0f + erff(v10 * kg));
            v11 = 0.5f * v11 * (1.0f + erff(v11 * kg));
            *reinterpret_cast<__half2*>(&Ahi[r0 * 136 + ncol]) = __floats2half2_rn(v00, v01);
            *reinterpret_cast<__half2*>(&Ahi[r1 * 136 + ncol]) = __floats2half2_rn(v10, v11);
        }
    }
    __syncthreads();

    // ---- phase C: eigf = eig + h1 @ ffn2W + b; masked column sums ----
    {
        float acc[4][4];
#pragma unroll
        for (int nt = 0; nt < 4; nt++)
#pragma unroll
            for (int i = 0; i < 4; i++) acc[nt][i] = 0.0f;
        gemm_tile(Ahi, &g_wf[5 * 4096], warp, lane, acc);
        const int sn = *snp;
#pragma unroll
        for (int nt = 0; nt < 4; nt++) {
            const int ncol = (4 * ch + nt) * 8 + 2 * t4;
            const int r0 = mt * 16 + g, r1 = r0 + 8;
            const int row0 = m0 + r0, row1 = m0 + r1;
            float b0 = f2b[ncol], b1 = f2b[ncol + 1];
            float v00 = acc[nt][0] + b0 + eigS[r0 * 132 + ncol];
            float v01 = acc[nt][1] + b1 + eigS[r0 * 132 + ncol + 1];
            float v10 = acc[nt][2] + b0 + eigS[r1 * 132 + ncol];
            float v11 = acc[nt][3] + b1 + eigS[r1 * 132 + ncol + 1];
            float a0 = (row0 < sn ? v00 : 0.0f) + (row1 < sn ? v10 : 0.0f);
            float a1 = (row0 < sn ? v01 : 0.0f) + (row1 < sn ? v11 : 0.0f);
            atomicAdd(&colsum[ncol], a0);
            atomicAdd(&colsum[ncol + 1], a1);
        }
    }
    __syncthreads();
    if (tid < 128) atomicAdd(&g_xsum[tid], (double)colsum[tid]);
}

// ============================================================================
// K1: sine encoding + GEMM  ->  g_eig = eeig[S,129] @ W[129,128] + b
// 16 rows per block, 256 threads (each thread: 8 rows of one column).
// ============================================================================
__global__ void __launch_bounds__(256) k_sine_enc(const float* __restrict__ eve,
                                                  const float* __restrict__ W,
                                                  const float* __restrict__ b) {
    __shared__ float ee[16][132];   // 129 used
    const int m0  = blockIdx.x * 16;
    const int tid = threadIdx.x;
    const float kLog = -9.210340371976184f / 128.0f;   // -ln(1e4)/128

    for (int idx = tid; idx < 16 * 64; idx += 256) {
        int r = idx >> 6, i = idx & 63;
        float e  = eve[m0 + r];
        float pe = e * 100.0f * __expf((2.0f * i) * kLog);
        float sv, cv;
        __sincosf(pe, &sv, &cv);
        ee[r][1 + i]  = sv;
        ee[r][65 + i] = cv;
    }
    if (tid < 16) ee[tid][0] = eve[m0 + tid];
    __syncthreads();

    const int col  = tid & 127;
    const int half = tid >> 7;     // 0: rows 0-7, 1: rows 8-15
    float acc[8];
#pragma unroll
    for (int r = 0; r < 8; r++) acc[r] = 0.0f;

    for (int k = 0; k < 129; k++) {
        float wv = W[k * HID + col];
#pragma unroll
        for (int r = 0; r < 8; r++) acc[r] = fmaf(ee[half * 8 + r][k], wv, acc[r]);
    }
    float bb = b[col];
#pragma unroll
    for (int r = 0; r < 8; r++)
        g_eig[(m0 + half * 8 + r) * HID + col] = acc[r] + bb;
}

// ============================================================================
// K4a: MMA flash attention partial. Fixed-reference softmax (M == 0):
// P = exp2(score) directly (clamped at 2^14); reference cancels in O/l.
// Fragment loads via ldmatrix.x4. QK 1-term, PV 1-term fp16; l via ones-row.
// grid = (S/QT, NHEADS, NKC), block = 256 (8 warps x 16 queries).
// ============================================================================
__global__ void __launch_bounds__(256) k_attn_mma(const float* __restrict__ qkv,
                                                  const int* __restrict__ snp) {
    __shared__ __align__(16) __half tile[2][TILE_H];

    const int tid  = threadIdx.x;
    const int warp = tid >> 5;
    const int lane = tid & 31;
    const int g    = lane >> 2;    // group (row within fragment)
    const int t4   = lane & 3;     // thread-in-group
    const int h    = blockIdx.y;
    const int kc   = blockIdx.z;
    const int sn   = *snp;

    const int qbase = blockIdx.x * QT + warp * 16;
    const int r0 = qbase + g;        // query rows owned by this thread
    const int r1 = r0 + 8;

    const uint32_t sm0 = (uint32_t)__cvta_generic_to_shared(&tile[0][0]);
    const uint32_t sm1 = (uint32_t)__cvta_generic_to_shared(&tile[1][0]);

    // lane-invariant ldmatrix byte offsets (within a tile buffer)
    const uint32_t qk_lane = (uint32_t)(((lane & 7) * KROW + (lane >> 3) * 8) * 2);
    const uint32_t pv_lane = (uint32_t)((KIMG + (lane & 7) * VROW + (lane >> 3) * 8) * 2);

    // ---- load Q fragments (2 k-steps), fp16 hi only; log2e folded in ----
    uint32_t Q[2][4];
#pragma unroll
    for (int ks = 0; ks < 2; ks++) {
#pragma unroll
        for (int hh = 0; hh < 2; hh++) {     // k-half (+0 / +8)
#pragma unroll
            for (int rr = 0; rr < 2; rr++) { // row g / g+8
                int row = rr ? r1 : r0;
                int d0  = ks * 16 + hh * 8 + 2 * t4;
                float x0 = qkv[row * 384 + h * HD + d0]     * QSCALE;
                float x1 = qkv[row * 384 + h * HD + d0 + 1] * QSCALE;
                Q[ks][hh * 2 + rr] = pack2f(x0, x1);
            }
        }
    }

    float O[5][4];                    // [d-tile][frag]; nt=4 carries l (ones row)
#pragma unroll
    for (int nt = 0; nt < 5; nt++)
#pragma unroll
        for (int i = 0; i < 4; i++) O[nt][i] = 0.0f;

    const int tile0 = (kc * CHUNK) >> 6;    // first tile index in this chunk

    // prefetch tile 0 into buffer 0
    {
        const uint4* src = reinterpret_cast<const uint4*>(
            g_kv + (size_t)(h * (S / KT) + tile0) * TILE_H);
        for (int i = tid; i < TILE_U4; i += 256)
            cp16(sm0 + i * 16, src + i);
        cp_commit();
    }

    for (int it = 0; it < NT_CH; it++) {
        cp_wait_all();
        __syncthreads();

        // prefetch next tile into the other buffer (overlaps compute below)
        if (it + 1 < NT_CH) {
            const uint4* src = reinterpret_cast<const uint4*>(
                g_kv + (size_t)(h * (S / KT) + tile0 + it + 1) * TILE_H);
            uint32_t dstb = ((it + 1) & 1) ? sm1 : sm0;
            for (int i = tid; i < TILE_U4; i += 256)
                cp16(dstb + i * 16, src + i);
            cp_commit();
        }

        const uint32_t smb = (it & 1) ? sm1 : sm0;
        const int kb = kc * CHUNK + it * KT;

        // ---- QK^T: 8 n-tiles of 8 keys; ldmatrix.x4 per tile (2 k-steps) ----
        float Sf[8][4];
#pragma unroll
        for (int nt = 0; nt < 8; nt++) {
#pragma unroll
            for (int i = 0; i < 4; i++) Sf[nt][i] = 0.0f;
            uint32_t b0, b1, b2, b3;
            ldm_x4(b0, b1, b2, b3, smb + qk_lane + nt * (8 * KROW * 2));
            mma16816(Sf[nt][0], Sf[nt][1], Sf[nt][2], Sf[nt][3],
                     Q[0][0], Q[0][1], Q[0][2], Q[0][3], b0, b1);
            mma16816(Sf[nt][0], Sf[nt][1], Sf[nt][2], Sf[nt][3],
                     Q[1][0], Q[1][1], Q[1][2], Q[1][3], b2, b3);
        }

        // ---- mask (only the boundary tile pays) ----
        if (kb + KT > sn) {
#pragma unroll
            for (int nt = 0; nt < 8; nt++) {
                int k0 = kb + nt * 8 + 2 * t4;
                if (k0     >= sn) { Sf[nt][0] = -INFINITY; Sf[nt][2] = -INFINITY; }
                if (k0 + 1 >= sn) { Sf[nt][1] = -INFINITY; Sf[nt][3] = -INFINITY; }
            }
        }

        // ---- P = exp2(score), fixed reference (no max, no rescale) ----
        uint32_t Ph[4][4];
#pragma unroll
        for (int j = 0; j < 4; j++) {       // key-step j covers tiles 2j, 2j+1
#pragma unroll
            for (int tt = 0; tt < 2; tt++) {
                int nt = 2 * j + tt;
                Ph[j][tt * 2]     = exp2h2c(Sf[nt][0], Sf[nt][1]);
                Ph[j][tt * 2 + 1] = exp2h2c(Sf[nt][2], Sf[nt][3]);
            }
        }

        // ---- PV: 5 d-tiles (incl. ones row) x 4 key-steps via ldmatrix ----
#pragma unroll
        for (int nt = 0; nt < 5; nt++) {
            const uint32_t abase = smb + pv_lane + nt * (8 * VROW * 2);
#pragma unroll
            for (int p = 0; p < 2; p++) {   // key-step pair
                uint32_t b0, b1, b2, b3;
                ldm_x4(b0, b1, b2, b3, abase + p * 64);
                mma16816(O[nt][0], O[nt][1], O[nt][2], O[nt][3],
                         Ph[2 * p][0], Ph[2 * p][1], Ph[2 * p][2], Ph[2 * p][3], b0, b1);
                mma16816(O[nt][0], O[nt][1], O[nt][2], O[nt][3],
                         Ph[2 * p + 1][0], Ph[2 * p + 1][1], Ph[2 * p + 1][2], Ph[2 * p + 1][3], b2, b3);
            }
        }
        __syncthreads();
    }

    // ---- write partials (unnormalized); l lives in O[4] at col 32 (t4==0) ----
    const int p0 = (h * NKC + kc) * S + r0;
    const int p1 = (h * NKC + kc) * S + r1;
    if (t4 == 0) {
        g_pl[p0] = O[4][0];
        g_pl[p1] = O[4][2];
    }
#pragma unroll
    for (int nt = 0; nt < 4; nt++) {
        int d = nt * 8 + 2 * t4;
        g_po[(size_t)p0 * HD + d]     = O[nt][0];
        g_po[(size_t)p0 * HD + d + 1] = O[nt][1];
        g_po[(size_t)p1 * HD + d]     = O[nt][2];
        g_po[(size_t)p1 * HD + d + 1] = O[nt][3];
    }
}

// ============================================================================
// pooled coefficients (single block)
// ============================================================================
__global__ void __launch_bounds__(128) k_pool(const float* __restrict__ dscW, const float* __restrict__ dscb,
                                              const float* __restrict__ dwvW, const float* __restrict__ dwvb,
                                              const float* __restrict__ dssW, const float* __restrict__ dssb,
                                              const int* __restrict__ lenp, const int* __restrict__ snp) {
    const int tid = threadIdx.x;
    __shared__ float sig[104];
    __shared__ float ssum[2];
    const float lenf = (float)(*lenp);
    const float snf  = (float)(*snp);

    if (tid < 104) {
        const float* W; const float* bb; int c; int NCc;
        if (tid < 50)       { W = dscW; bb = dscb; c = tid;       NCc = NCOE; }
        else if (tid < 100) { W = dwvW; bb = dwvb; c = tid - 50;  NCc = NCOE; }
        else                { W = dssW; bb = dssb; c = tid - 100; NCc = NSCALES; }
        double acc = 0.0;
        for (int k = 0; k < HID; k++) acc += g_xsum[k] * (double)W[k * NCc + c];
        float pooled = (float)((acc + (double)(snf * bb[c])) / (double)(lenf + 1e-8f));
        sig[tid] = 1.0f / (1.0f + expf(-pooled));
    }
    __syncthreads();
    if (tid == 0) { float t = 0.f; for (int i = 0;  i < 50;  i++) t += sig[i]; ssum[0] = t; }
    if (tid == 1) { float t = 0.f; for (int i = 50; i < 100; i++) t += sig[i]; ssum[1] = t; }
    __syncthreads();
    if (tid < 50)       g_coef[tid] = sig[tid] / (ssum[0] + 1e-8f);
    else if (tid < 100) g_coef[tid] = sig[tid] / (ssum[1] + 1e-8f);
    else if (tid < 104) g_coef[tid] = sig[tid] * 5.0f;   // THRE
}

// ============================================================================
// Chebyshev synthesis + L2 normalize  ->  out[S, 5]
// ============================================================================
__global__ void __launch_bounds__(128) k_final(const float* __restrict__ eve,
                                               float* __restrict__ out) {
    __shared__ float cs[NCOE], cw[NCOE], sc[NSCALES];
    const int tid = threadIdx.x;
    if (tid < 50)        cs[tid]       = g_coef[tid];
    else if (tid < 100)  cw[tid - 50]  = g_coef[tid];
    else if (tid < 104)  sc[tid - 100] = g_coef[tid];
    __syncthreads();

    const int s = blockIdx.x * 128 + tid;
    const float e = eve[s];
    float vals[5];

    {   // scaling channel: y = e - 1; coefficients on T_1,T_3,...
        float y  = e - 1.0f;
        float te = 1.0f, to = y;
        float acc = cs[0] * (0.5f * (1.0f - to));
#pragma unroll
        for (int c = 1; c < NCOE; c++) {
            te = 2.0f * y * to - te;          // T_{2c}
            to = 2.0f * y * te - to;          // T_{2c+1}
            acc += cs[c] * (0.5f * (1.0f - to));
        }
        vals[0] = acc;
    }

#pragma unroll
    for (int j = 0; j < NSCALES; j++) {       // wavelet channels: T_0,T_2,...
        float f = e * sc[j];
        if (f > 2.0f) f = 0.0f;
        float y  = f - 1.0f;
        float te = 1.0f, to = y;
        float acc = 0.0f;                      // cw[0] * 0.5*(1-T_0) = 0
#pragma unroll
        for (int c = 1; c < NCOE; c++) {
            te = 2.0f * y * to - te;          // T_{2c}
            acc += cw[c] * (0.5f * (1.0f - te));
            to = 2.0f * y * te - to;          // T_{2c+1}
        }
        vals[1 + j] = acc;
    }

    float n2 = 0.0f;
#pragma unroll
    for (int i = 0; i < 5; i++) n2 += vals[i] * vals[i];
    float inv = 1.0f / (sqrtf(n2) + 1e-8f);
#pragma unroll
    for (int i = 0; i < 5; i++) out[s * 5 + i] = vals[i] * inv;
}

// ============================================================================
// launch
// ============================================================================
extern "C" void kernel_launch(void* const* d_in, const int* in_sizes, int n_in,
                              void* d_out, int out_size) {
    const float* eve      = (const float*)d_in[0];
    const int*   lenp     = (const int*)  d_in[1];
    const int*   snp      = (const int*)  d_in[2];
    const float* eig_w_W  = (const float*)d_in[3];
    const float* eig_w_b  = (const float*)d_in[4];
    const float* mha_ln_g = (const float*)d_in[5];
    const float* mha_ln_b = (const float*)d_in[6];
    const float* in_W     = (const float*)d_in[7];
    const float* in_b     = (const float*)d_in[8];
    const float* out_W    = (const float*)d_in[9];
    const float* out_b    = (const float*)d_in[10];
    const float* ffn_ln_g = (const float*)d_in[11];
    const float* ffn_ln_b = (const float*)d_in[12];
    const float* ffn1_W   = (const float*)d_in[13];
    const float* ffn1_b   = (const float*)d_in[14];
    const float* ffn2_W   = (const float*)d_in[15];
    const float* ffn2_b   = (const float*)d_in[16];
    const float* dsc_W    = (const float*)d_in[17];
    const float* dsc_b    = (const float*)d_in[18];
    const float* dwv_W    = (const float*)d_in[19];
    const float* dwv_b    = (const float*)d_in[20];
    const float* dss_W    = (const float*)d_in[21];
    const float* dss_b    = (const float*)d_in[22];
    float* out = (float*)d_out;

    float *p_eig, *p_qkv;
    cudaGetSymbolAddress((void**)&p_eig,  g_eig);
    cudaGetSymbolAddress((void**)&p_qkv,  g_qkv);

    // 0) weight images + zero xsum + static g_kv content (ones rows, pads)
    k_wprep<<<dim3(16, 6), 256>>>(in_W, out_W, ffn1_W, ffn2_W);
    // 1) eig = sine_encoding(eve) @ W + b
    k_sine_enc<<<S / 16, 256>>>(eve, eig_w_W, eig_w_b);
    // 2) qkv: Q -> float g_qkv; K/V -> fp16 g_kv images directly
    k_qkv_mma<<<dim3(128, 3), 256>>>(p_eig, in_b, p_qkv, mha_ln_g, mha_ln_b);
    // 3) attention split-K partials
    k_attn_mma<<<dim3(S / QT, NHEADS, NKC), 256>>>(p_qkv, snp);
    // 4) fused: combine -> out-proj(+resid) -> LN -> ffn1+gelu -> ffn2(+resid) -> colsums
    k_ffn_fused<<<dim3(128), 256>>>(out_b, ffn1_b, ffn2_b, ffn_ln_g, ffn_ln_b, snp);
    // 5) pooled coefficients
    k_pool<<<1, 128>>>(dsc_W, dsc_b, dwv_W, dwv_b, dss_W, dss_b, lenp, snp);
    // 6) Chebyshev synthesis + normalize
    k_final<<<S / 128, 128>>>(eve, out);
}

// round 17
// speedup vs baseline: 1.0766x; 1.0766x over previous
#include <cuda_runtime.h>
#include <cuda_fp16.h>
#include <math.h>
#include <stdint.h>

// ---------------- problem constants ----------------
#define S 4096
#define HID 128
#define NHEADS 4
#define NCOE 50
#define NSCALES 4
#define NKC 2              // split-K chunks for attention
#define CHUNK (S / NKC)    // 2048 keys per chunk
#define QT 128             // queries per block (8 warps x 16)
#define KT 64              // key tile
#define NT_CH (CHUNK / KT) // 32 tiles per chunk
#define HD 32

// KV tile image geometry (halves). KROW*2 must be a multiple of 16 bytes
// (ldmatrix row alignment) and conflict-free: KROW = 40 (80 B rows).
#define KROW 40                      // per-key: 32 hi + 8 pad (pad never read)
#define KIMG (KT * KROW)             // 2560 halves
#define VROW 72                      // per-dim: 64 keys + 8 pad (144 B, aligned)
#define VSTAGE 33                    // V rows staged: 32 V + 1 ones row
#define TILE_H (KIMG + VSTAGE * VROW)   // 4936 halves = 9872 B
#define TILE_U4 (TILE_H / 8)            // 617 uint4
#define TILE_STRIDE 5440             // smem buffer stride (halves); covers nt=4 ldsm overread (max 5432)
#define NIMG (NHEADS * (S / KT))     // 256 images
#define ONES_OFF (KIMG + 32 * VROW)  // 4864 halves; uint4 slot 608

// log2(e)/sqrt(32): scores come out of QK in log2 domain
#define QSCALE 0.2550458572864341f

// ---------------- scratch (__device__ globals; no allocs allowed) ----------------
__device__ float  g_eig [S * HID];
__device__ float  g_qkv [S * 3 * HID];   // only Q region (cols 0..127) used
__device__ __align__(16) __half g_kv[NIMG * TILE_H];  // pre-swizzled K/V tiles
__device__ __align__(16) uint4  g_wf[6 * 4096];   // 6 weight images, fragment-ordered
__device__ float  g_pl  [NHEADS * NKC * S];        // partial sum (fixed-ref softmax)
__device__ float  g_po  [NHEADS * NKC * S * HD];   // partial (unnormalized) out
__device__ double g_xsum[HID];

// ---------------- mma / async helpers ----------------
__device__ __forceinline__ void mma16816(float& c0, float& c1, float& c2, float& c3,
                                         uint32_t a0, uint32_t a1, uint32_t a2, uint32_t a3,
                                         uint32_t b0, uint32_t b1) {
    asm volatile("mma.sync.aligned.m16n8k16.row.col.f32.f16.f16.f32 "
                 "{%0,%1,%2,%3}, {%4,%5,%6,%7}, {%8,%9}, {%0,%1,%2,%3};\n"
                 : "+f"(c0), "+f"(c1), "+f"(c2), "+f"(c3)
                 : "r"(a0), "r"(a1), "r"(a2), "r"(a3), "r"(b0), "r"(b1));
}

__device__ __forceinline__ void ldm_x4(uint32_t& d0, uint32_t& d1, uint32_t& d2, uint32_t& d3,
                                       uint32_t addr) {
    asm volatile("ldmatrix.sync.aligned.m8n8.x4.shared.b16 {%0,%1,%2,%3}, [%4];\n"
                 : "=r"(d0), "=r"(d1), "=r"(d2), "=r"(d3) : "r"(addr));
}

__device__ __forceinline__ void cp16(uint32_t dst, const void* src) {
    asm volatile("cp.async.cg.shared.global [%0], [%1], 16;\n" :: "r"(dst), "l"(src));
}
__device__ __forceinline__ void cp_commit() {
    asm volatile("cp.async.commit_group;\n");
}
__device__ __forceinline__ void cp_wait_all() {
    asm volatile("cp.async.wait_group 0;\n");
}

__device__ __forceinline__ uint32_t packh2(__half a, __half b) {
    __half2 t = __halves2half2(a, b);     // a -> low half
    return *reinterpret_cast<uint32_t*>(&t);
}

// split x into hi (fp16) and lo (fp16 of remainder)
__device__ __forceinline__ void hsplit(float x, __half& h, __half& l) {
    h = __float2half_rn(x);
    l = __float2half_rn(x - __half2float(h));
}

__device__ __forceinline__ uint32_t pack2f(float x, float y) {
    __half2 t = __floats2half2_rn(x, y);  // x -> low
    return *reinterpret_cast<uint32_t*>(&t);
}

// 2^a, 2^b as packed fp16x2, clamped at 14.0 (2^14 < fp16 max). -inf -> 0.
__device__ __forceinline__ uint32_t exp2h2c(float a, float b) {
    uint32_t p = pack2f(a, b);
    uint32_t c, r;
    asm("min.f16x2 %0, %1, %2;" : "=r"(c) : "r"(p), "r"(0x4B004B00u));  // 14.0|14.0
    asm("ex2.approx.f16x2 %0, %1;" : "=r"(r) : "r"(c));
    return r;
}

// ============================================================================
// Prep0: merged weight-prep + sine-encoding kernel.
// blocks [0,96): fragment-ordered fp16 hi/lo weight images (+ g_xsum zero,
//                + g_kv ones-row init).
// blocks [96,352): sine encoding + GEMM -> g_eig (16 rows per block).
// 256 threads.
// ============================================================================
__global__ void __launch_bounds__(256) k_prep0(const float* __restrict__ inW,
                                               const float* __restrict__ outW,
                                               const float* __restrict__ f1W,
                                               const float* __restrict__ f2W,
                                               const float* __restrict__ eve,
                                               const float* __restrict__ eW,
                                               const float* __restrict__ eb) {
    const int tid = threadIdx.x;

    if (blockIdx.x < 96) {
        const int bx = blockIdx.x & 15;      // 0..15
        const int by = blockIdx.x >> 4;      // 0..5
        if (blockIdx.x == 0 && tid < HID) g_xsum[tid] = 0.0;

        // ones rows: 256 images x 8 uint4 = 2048, grid-stride over 96x256
        {
            const uint4 ones4 = make_uint4(0x3C003C00u, 0x3C003C00u, 0x3C003C00u, 0x3C003C00u);
            uint4* kvp = reinterpret_cast<uint4*>(g_kv);
            for (int i = blockIdx.x * 256 + tid; i < NIMG * 8; i += 96 * 256) {
                int img = i >> 3, k = i & 7;
                kvp[img * TILE_U4 + (ONES_OFF / 8) + k] = ones4;
            }
        }

        const int lane = tid & 31;
        const int g    = lane >> 2;
        const int t4   = lane & 3;
        const int wid  = bx * 8 + (tid >> 5);   // fragment id 0..127
        const int nt   = wid >> 3;
        const int ks   = wid & 7;

        const float* W; int ldw, c0;
        switch (by) {
            case 0:  W = inW;  ldw = 384; c0 = 0;   break;
            case 1:  W = inW;  ldw = 384; c0 = 128; break;
            case 2:  W = inW;  ldw = 384; c0 = 256; break;
            case 3:  W = outW; ldw = 128; c0 = 0;   break;
            case 4:  W = f1W;  ldw = 128; c0 = 0;   break;
            default: W = f2W;  ldw = 128; c0 = 0;   break;
        }

        const int n  = nt * 8 + g;
        const int k0 = ks * 16 + 2 * t4;
        float w00 = W[(k0    ) * ldw + c0 + n];
        float w01 = W[(k0 + 1) * ldw + c0 + n];
        float w80 = W[(k0 + 8) * ldw + c0 + n];
        float w81 = W[(k0 + 9) * ldw + c0 + n];
        __half h00, l00, h01, l01, h80, l80, h81, l81;
        hsplit(w00, h00, l00);  hsplit(w01, h01, l01);
        hsplit(w80, h80, l80);  hsplit(w81, h81, l81);
        uint4 f;
        f.x = packh2(h00, h01);
        f.y = packh2(h80, h81);
        f.z = packh2(l00, l01);
        f.w = packh2(l80, l81);
        g_wf[by * 4096 + wid * 32 + lane] = f;
    } else {
        // ---- sine encoding + GEMM ----
        __shared__ float ee[16][132];   // 129 used
        const int m0 = (blockIdx.x - 96) * 16;
        const float kLog = -9.210340371976184f / 128.0f;   // -ln(1e4)/128

        for (int idx = tid; idx < 16 * 64; idx += 256) {
            int r = idx >> 6, i = idx & 63;
            float e  = eve[m0 + r];
            float pe = e * 100.0f * __expf((2.0f * i) * kLog);
            float sv, cv;
            __sincosf(pe, &sv, &cv);
            ee[r][1 + i]  = sv;
            ee[r][65 + i] = cv;
        }
        if (tid < 16) ee[tid][0] = eve[m0 + tid];
        __syncthreads();

        const int col  = tid & 127;
        const int half = tid >> 7;     // 0: rows 0-7, 1: rows 8-15
        float acc[8];
#pragma unroll
        for (int r = 0; r < 8; r++) acc[r] = 0.0f;

        for (int k = 0; k < 129; k++) {
            float wv = eW[k * HID + col];
#pragma unroll
            for (int r = 0; r < 8; r++) acc[r] = fmaf(ee[half * 8 + r][k], wv, acc[r]);
        }
        float bb = eb[col];
#pragma unroll
        for (int r = 0; r < 8; r++)
            g_eig[(m0 + half * 8 + r) * HID + col] = acc[r] + bb;
    }
}

// ============================================================================
// 2-term MMA helper: acc += Ah(32x128 smem tile, row stride 136) @ Wimg
// ============================================================================
__device__ __forceinline__ void gemm_tile(const __half* __restrict__ Ahi,
                                          const uint4* __restrict__ img_p,
                                          int warp, int lane, float acc[4][4]) {
    const int g = lane >> 2, t4 = lane & 3;
    const int mt = warp & 1, ch = warp >> 1;
    const __half* ahb = &Ahi[(mt * 16 + g) * 136];
#pragma unroll
    for (int ks = 0; ks < 8; ks++) {
        const int co = ks * 16 + 2 * t4;
        uint32_t ah0 = *reinterpret_cast<const uint32_t*>(&ahb[co]);
        uint32_t ah1 = *reinterpret_cast<const uint32_t*>(&ahb[8 * 136 + co]);
        uint32_t ah2 = *reinterpret_cast<const uint32_t*>(&ahb[co + 8]);
        uint32_t ah3 = *reinterpret_cast<const uint32_t*>(&ahb[8 * 136 + co + 8]);
#pragma unroll
        for (int nt = 0; nt < 4; nt++) {
            uint4 f = img_p[((4 * ch + nt) * 8 + ks) * 32 + lane];
            mma16816(acc[nt][0], acc[nt][1], acc[nt][2], acc[nt][3],
                     ah0, ah1, ah2, ah3, f.x, f.y);
            mma16816(acc[nt][0], acc[nt][1], acc[nt][2], acc[nt][3],
                     ah0, ah1, ah2, ah3, f.z, f.w);
        }
    }
}

// ============================================================================
// qkv GEMM: Q -> float g_qkv; K/V -> fp16 g_kv images.
// grid = (128, 3), 256 threads. LN fused in staging.
// ============================================================================
__global__ void __launch_bounds__(256) k_qkv_mma(const float* __restrict__ A,
                                                 const float* __restrict__ bias,
                                                 float* __restrict__ C,
                                                 const float* __restrict__ lng,
                                                 const float* __restrict__ lnb) {
    __shared__ __align__(16) __half Ahi[32 * 136];
    const int tid = threadIdx.x;
    const int m0  = blockIdx.x * 32;
    const int c0  = blockIdx.y * 128;

    // ---- stage LN(A) tile, fp16 hi ----
    {
        const int r = tid >> 3, l8 = tid & 7;
        float x[16];
        const float4* ap = reinterpret_cast<const float4*>(A + (m0 + r) * HID + l8 * 16);
#pragma unroll
        for (int j = 0; j < 4; j++) {
            float4 v = ap[j];
            x[j * 4 + 0] = v.x; x[j * 4 + 1] = v.y;
            x[j * 4 + 2] = v.z; x[j * 4 + 3] = v.w;
        }
        float s = 0.0f, s2 = 0.0f;
#pragma unroll
        for (int j = 0; j < 16; j++) { s += x[j]; s2 += x[j] * x[j]; }
#pragma unroll
        for (int o = 4; o; o >>= 1) {
            s  += __shfl_xor_sync(0xffffffffu, s,  o);
            s2 += __shfl_xor_sync(0xffffffffu, s2, o);
        }
        float mean = s * (1.0f / HID);
        float rstd = rsqrtf(s2 * (1.0f / HID) - mean * mean + 1e-5f);
        uint32_t phi[8];
#pragma unroll
        for (int j = 0; j < 8; j++) {
            int cA = l8 * 16 + 2 * j, cB = cA + 1;
            float xa = (x[2 * j]     - mean) * rstd * lng[cA] + lnb[cA];
            float xb = (x[2 * j + 1] - mean) * rstd * lng[cB] + lnb[cB];
            phi[j] = pack2f(xa, xb);
        }
        uint4* dhi = reinterpret_cast<uint4*>(&Ahi[r * 136 + l8 * 16]);
        dhi[0] = make_uint4(phi[0], phi[1], phi[2], phi[3]);
        dhi[1] = make_uint4(phi[4], phi[5], phi[6], phi[7]);
    }
    __syncthreads();

    const int warp = tid >> 5, lane = tid & 31;
    float acc[4][4];
#pragma unroll
    for (int nt = 0; nt < 4; nt++)
#pragma unroll
        for (int i = 0; i < 4; i++) acc[nt][i] = 0.0f;
    gemm_tile(Ahi, &g_wf[(size_t)blockIdx.y * 4096], warp, lane, acc);

    const int g = lane >> 2, t4 = lane & 3;
    const int mt = warp & 1, ch = warp >> 1;
#pragma unroll
    for (int nt = 0; nt < 4; nt++) {
        const int ncol = c0 + (4 * ch + nt) * 8 + 2 * t4;
        const int row0 = m0 + mt * 16 + g, row1 = row0 + 8;
        float b0 = bias[ncol], b1 = bias[ncol + 1];
        float v00 = acc[nt][0] + b0, v01 = acc[nt][1] + b1;
        float v10 = acc[nt][2] + b0, v11 = acc[nt][3] + b1;
        if (blockIdx.y == 0) {
            C[row0 * 384 + ncol]     = v00;
            C[row0 * 384 + ncol + 1] = v01;
            C[row1 * 384 + ncol]     = v10;
            C[row1 * 384 + ncol + 1] = v11;
        } else {
            const int lc   = ncol - c0;
            const int head = lc >> 5, d = lc & 31;
            const size_t base = (size_t)(head * (S / KT) + (row0 >> 6)) * TILE_H;
            const int key0 = row0 & 63, key1 = row1 & 63;
            if (blockIdx.y == 1) {
                *reinterpret_cast<__half2*>(&g_kv[base + key0 * KROW + d]) =
                    __floats2half2_rn(v00, v01);
                *reinterpret_cast<__half2*>(&g_kv[base + key1 * KROW + d]) =
                    __floats2half2_rn(v10, v11);
            } else {
                g_kv[base + KIMG + d * VROW + key0]       = __float2half_rn(v00);
                g_kv[base + KIMG + (d + 1) * VROW + key0] = __float2half_rn(v01);
                g_kv[base + KIMG + d * VROW + key1]       = __float2half_rn(v10);
                g_kv[base + KIMG + (d + 1) * VROW + key1] = __float2half_rn(v11);
            }
        }
    }
}

// ============================================================================
// MMA flash attention partial. Fixed-reference softmax (P = exp2(score),
// clamped at 2^14). ldmatrix.x4 fragments. QK 1-term, PV 1-term fp16;
// l via ones-row (nt=4 d-tile; overread rows feed unused accumulators only).
// grid = (S/QT, NHEADS, NKC), block = 256 (8 warps x 16 queries).
// ============================================================================
__global__ void __launch_bounds__(256) k_attn_mma(const float* __restrict__ qkv,
                                                  const int* __restrict__ snp) {
    __shared__ __align__(16) __half tile[2][TILE_STRIDE];

    const int tid  = threadIdx.x;
    const int warp = tid >> 5;
    const int lane = tid & 31;
    const int g    = lane >> 2;
    const int t4   = lane & 3;
    const int h    = blockIdx.y;
    const int kc   = blockIdx.z;
    const int sn   = *snp;

    const int qbase = blockIdx.x * QT + warp * 16;
    const int r0 = qbase + g;
    const int r1 = r0 + 8;

    const uint32_t sm0 = (uint32_t)__cvta_generic_to_shared(&tile[0][0]);
    const uint32_t sm1 = (uint32_t)__cvta_generic_to_shared(&tile[1][0]);

    // lane-invariant ldmatrix byte offsets (within a tile buffer)
    const uint32_t qk_lane = (uint32_t)(((lane & 7) * KROW + (lane >> 3) * 8) * 2);
    const uint32_t pv_lane = (uint32_t)((KIMG + (lane & 7) * VROW + (lane >> 3) * 8) * 2);

    // ---- load Q fragments (2 k-steps), fp16 hi only; log2e folded in ----
    uint32_t Q[2][4];
#pragma unroll
    for (int ks = 0; ks < 2; ks++) {
#pragma unroll
        for (int hh = 0; hh < 2; hh++) {
#pragma unroll
            for (int rr = 0; rr < 2; rr++) {
                int row = rr ? r1 : r0;
                int d0  = ks * 16 + hh * 8 + 2 * t4;
                float x0 = qkv[row * 384 + h * HD + d0]     * QSCALE;
                float x1 = qkv[row * 384 + h * HD + d0 + 1] * QSCALE;
                Q[ks][hh * 2 + rr] = pack2f(x0, x1);
            }
        }
    }

    float O[5][4];                    // [d-tile][frag]; nt=4 carries l (ones row)
#pragma unroll
    for (int nt = 0; nt < 5; nt++)
#pragma unroll
        for (int i = 0; i < 4; i++) O[nt][i] = 0.0f;

    const int tile0 = (kc * CHUNK) >> 6;

    // prefetch tile 0 into buffer 0
    {
        const uint4* src = reinterpret_cast<const uint4*>(
            g_kv + (size_t)(h * (S / KT) + tile0) * TILE_H);
        for (int i = tid; i < TILE_U4; i += 256)
            cp16(sm0 + i * 16, src + i);
        cp_commit();
    }

    for (int it = 0; it < NT_CH; it++) {
        cp_wait_all();
        __syncthreads();

        if (it + 1 < NT_CH) {
            const uint4* src = reinterpret_cast<const uint4*>(
                g_kv + (size_t)(h * (S / KT) + tile0 + it + 1) * TILE_H);
            uint32_t dstb = ((it + 1) & 1) ? sm1 : sm0;
            for (int i = tid; i < TILE_U4; i += 256)
                cp16(dstb + i * 16, src + i);
            cp_commit();
        }

        const uint32_t smb = (it & 1) ? sm1 : sm0;
        const int kb = kc * CHUNK + it * KT;

        // ---- QK^T: 8 n-tiles of 8 keys; ldmatrix.x4 per tile ----
        float Sf[8][4];
#pragma unroll
        for (int nt = 0; nt < 8; nt++) {
#pragma unroll
            for (int i = 0; i < 4; i++) Sf[nt][i] = 0.0f;
            uint32_t b0, b1, b2, b3;
            ldm_x4(b0, b1, b2, b3, smb + qk_lane + nt * (8 * KROW * 2));
            mma16816(Sf[nt][0], Sf[nt][1], Sf[nt][2], Sf[nt][3],
                     Q[0][0], Q[0][1], Q[0][2], Q[0][3], b0, b1);
            mma16816(Sf[nt][0], Sf[nt][1], Sf[nt][2], Sf[nt][3],
                     Q[1][0], Q[1][1], Q[1][2], Q[1][3], b2, b3);
        }

        // ---- mask (only the boundary tile pays) ----
        if (kb + KT > sn) {
#pragma unroll
            for (int nt = 0; nt < 8; nt++) {
                int k0 = kb + nt * 8 + 2 * t4;
                if (k0     >= sn) { Sf[nt][0] = -INFINITY; Sf[nt][2] = -INFINITY; }
                if (k0 + 1 >= sn) { Sf[nt][1] = -INFINITY; Sf[nt][3] = -INFINITY; }
            }
        }

        // ---- P = exp2(score), fixed reference ----
        uint32_t Ph[4][4];
#pragma unroll
        for (int j = 0; j < 4; j++) {
#pragma unroll
            for (int tt = 0; tt < 2; tt++) {
                int nt = 2 * j + tt;
                Ph[j][tt * 2]     = exp2h2c(Sf[nt][0], Sf[nt][1]);
                Ph[j][tt * 2 + 1] = exp2h2c(Sf[nt][2], Sf[nt][3]);
            }
        }

        // ---- PV: 5 d-tiles (incl. ones row) x 4 key-steps via ldmatrix ----
#pragma unroll
        for (int nt = 0; nt < 5; nt++) {
            const uint32_t abase = smb + pv_lane + nt * (8 * VROW * 2);
#pragma unroll
            for (int p = 0; p < 2; p++) {
                uint32_t b0, b1, b2, b3;
                ldm_x4(b0, b1, b2, b3, abase + p * 64);
                mma16816(O[nt][0], O[nt][1], O[nt][2], O[nt][3],
                         Ph[2 * p][0], Ph[2 * p][1], Ph[2 * p][2], Ph[2 * p][3], b0, b1);
                mma16816(O[nt][0], O[nt][1], O[nt][2], O[nt][3],
                         Ph[2 * p + 1][0], Ph[2 * p + 1][1], Ph[2 * p + 1][2], Ph[2 * p + 1][3], b2, b3);
            }
        }
        __syncthreads();
    }

    // ---- write partials (unnormalized); l lives in O[4] at col 32 (t4==0) ----
    const int p0 = (h * NKC + kc) * S + r0;
    const int p1 = (h * NKC + kc) * S + r1;
    if (t4 == 0) {
        g_pl[p0] = O[4][0];
        g_pl[p1] = O[4][2];
    }
#pragma unroll
    for (int nt = 0; nt < 4; nt++) {
        int d = nt * 8 + 2 * t4;
        g_po[(size_t)p0 * HD + d]     = O[nt][0];
        g_po[(size_t)p0 * HD + d + 1] = O[nt][1];
        g_po[(size_t)p1 * HD + d]     = O[nt][2];
        g_po[(size_t)p1 * HD + d + 1] = O[nt][3];
    }
}

// ============================================================================
// Fused post-attention chain, all row-local per 32-row block:
// combine(partials) -> @outW (+eig resid) -> LN -> @ffn1W + gelu -> @ffn2W
// (+eig resid) -> masked column sums into g_xsum.
// grid = 128, 256 threads.
// ============================================================================
__global__ void __launch_bounds__(256) k_ffn_fused(const float* __restrict__ outb,
                                                   const float* __restrict__ f1b,
                                                   const float* __restrict__ f2b,
                                                   const float* __restrict__ lng,
                                                   const float* __restrict__ lnb,
                                                   const int* __restrict__ snp) {
    __shared__ __align__(16) __half Ahi[32 * 136];
    __shared__ float eigS[32 * 132];
    __shared__ float colsum[128];
    const int tid = threadIdx.x;
    const int m0  = blockIdx.x * 32;
    const int warp = tid >> 5, lane = tid & 31;
    const int g = lane >> 2, t4 = lane & 3;
    const int mt = warp & 1, ch = warp >> 1;

    for (int i = tid; i < 32 * 32; i += 256) {
        int r = i >> 5, c4 = i & 31;
        float4 v = *reinterpret_cast<const float4*>(&g_eig[(m0 + r) * HID + c4 * 4]);
        *reinterpret_cast<float4*>(&eigS[r * 132 + c4 * 4]) = v;
    }
    if (tid < 128) colsum[tid] = 0.0f;

    // ---- stage attention combine (fixed-ref: plain sums) ----
    {
        const int r = tid >> 3, l8 = tid & 7;
        const int row    = m0 + r;
        const int head   = l8 >> 1;
        const int hd_off = (l8 & 1) * 16;
        float x[16];
#pragma unroll
        for (int j = 0; j < 16; j++) x[j] = 0.0f;
        float L = 0.0f;
#pragma unroll
        for (int kc = 0; kc < NKC; kc++) {
            const int p = (head * NKC + kc) * S + row;
            L += g_pl[p];
            const float4* po = reinterpret_cast<const float4*>(&g_po[(size_t)p * HD + hd_off]);
#pragma unroll
            for (int jj = 0; jj < 4; jj++) {
                float4 v = po[jj];
                x[jj * 4 + 0] += v.x;
                x[jj * 4 + 1] += v.y;
                x[jj * 4 + 2] += v.z;
                x[jj * 4 + 3] += v.w;
            }
        }
        float inv = (L > 0.0f) ? 1.0f / L : 0.0f;
        uint32_t phi[8];
#pragma unroll
        for (int j = 0; j < 8; j++)
            phi[j] = pack2f(x[2 * j] * inv, x[2 * j + 1] * inv);
        uint4* dhi = reinterpret_cast<uint4*>(&Ahi[r * 136 + l8 * 16]);
        dhi[0] = make_uint4(phi[0], phi[1], phi[2], phi[3]);
        dhi[1] = make_uint4(phi[4], phi[5], phi[6], phi[7]);
    }
    __syncthreads();

    // ---- phase A: out-proj; eig += att @ outW + b ----
    {
        float acc[4][4];
#pragma unroll
        for (int nt = 0; nt < 4; nt++)
#pragma unroll
            for (int i = 0; i < 4; i++) acc[nt][i] = 0.0f;
        gemm_tile(Ahi, &g_wf[3 * 4096], warp, lane, acc);
#pragma unroll
        for (int nt = 0; nt < 4; nt++) {
            const int ncol = (4 * ch + nt) * 8 + 2 * t4;
            const int r0 = mt * 16 + g, r1 = r0 + 8;
            float b0 = outb[ncol], b1 = outb[ncol + 1];
            eigS[r0 * 132 + ncol]     += acc[nt][0] + b0;
            eigS[r0 * 132 + ncol + 1] += acc[nt][1] + b1;
            eigS[r1 * 132 + ncol]     += acc[nt][2] + b0;
            eigS[r1 * 132 + ncol + 1] += acc[nt][3] + b1;
        }
    }
    __syncthreads();

    // ---- stage LN(eigS) -> Ahi ----
    {
        const int r = tid >> 3, l8 = tid & 7;
        float x[16];
#pragma unroll
        for (int j = 0; j < 16; j++) x[j] = eigS[r * 132 + l8 * 16 + j];
        float s = 0.0f, s2 = 0.0f;
#pragma unroll
        for (int j = 0; j < 16; j++) { s += x[j]; s2 += x[j] * x[j]; }
#pragma unroll
        for (int o = 4; o; o >>= 1) {
            s  += __shfl_xor_sync(0xffffffffu, s,  o);
            s2 += __shfl_xor_sync(0xffffffffu, s2, o);
        }
        float mean = s * (1.0f / HID);
        float rstd = rsqrtf(s2 * (1.0f / HID) - mean * mean + 1e-5f);
        uint32_t phi[8];
#pragma unroll
        for (int j = 0; j < 8; j++) {
            int cA = l8 * 16 + 2 * j, cB = cA + 1;
            float xa = (x[2 * j]     - mean) * rstd * lng[cA] + lnb[cA];
            float xb = (x[2 * j + 1] - mean) * rstd * lng[cB] + lnb[cB];
            phi[j] = pack2f(xa, xb);
        }
        uint4* dhi = reinterpret_cast<uint4*>(&Ahi[r * 136 + l8 * 16]);
        dhi[0] = make_uint4(phi[0], phi[1], phi[2], phi[3]);
        dhi[1] = make_uint4(phi[4], phi[5], phi[6], phi[7]);
    }
    __syncthreads();

    // ---- phase B: h1 = gelu(LN @ ffn1W + b); restage into Ahi ----
    {
        float acc[4][4];
#pragma unroll
        for (int nt = 0; nt < 4; nt++)
#pragma unroll
            for (int i = 0; i < 4; i++) acc[nt][i] = 0.0f;
        gemm_tile(Ahi, &g_wf[4 * 4096], warp, lane, acc);
        __syncthreads();   // all reads of Ahi done before overwrite
        const float kg = 0.70710678118654752f;
#pragma unroll
        for (int nt = 0; nt < 4; nt++) {
            const int ncol = (4 * ch + nt) * 8 + 2 * t4;
            const int r0 = mt * 16 + g, r1 = r0 + 8;
            float b0 = f1b[ncol], b1 = f1b[ncol + 1];
            float v00 = acc[nt][0] + b0, v01 = acc[nt][1] + b1;
            float v10 = acc[nt][2] + b0, v11 = acc[nt][3] + b1;
            v00 = 0.5f * v00 * (1.0f + erff(v00 * kg));
            v01 = 0.5f * v01 * (1.0f + erff(v01 * kg));
            v10 = 0.5f * v10 * (1.0f + erff(v10 * kg));
            v11 = 0.5f * v11 * (1.0f + erff(v11 * kg));
            *reinterpret_cast<__half2*>(&Ahi[r0 * 136 + ncol]) = __floats2half2_rn(v00, v01);
            *reinterpret_cast<__half2*>(&Ahi[r1 * 136 + ncol]) = __floats2half2_rn(v10, v11);
        }
    }
    __syncthreads();

    // ---- phase C: eigf = eig + h1 @ ffn2W + b; masked column sums ----
    {
        float acc[4][4];
#pragma unroll
        for (int nt = 0; nt < 4; nt++)
#pragma unroll
            for (int i = 0; i < 4; i++) acc[nt][i] = 0.0f;
        gemm_tile(Ahi, &g_wf[5 * 4096], warp, lane, acc);
        const int sn = *snp;
#pragma unroll
        for (int nt = 0; nt < 4; nt++) {
            const int ncol = (4 * ch + nt) * 8 + 2 * t4;
            const int r0 = mt * 16 + g, r1 = r0 + 8;
            const int row0 = m0 + r0, row1 = m0 + r1;
            float b0 = f2b[ncol], b1 = f2b[ncol + 1];
            float v00 = acc[nt][0] + b0 + eigS[r0 * 132 + ncol];
            float v01 = acc[nt][1] + b1 + eigS[r0 * 132 + ncol + 1];
            float v10 = acc[nt][2] + b0 + eigS[r1 * 132 + ncol];
            float v11 = acc[nt][3] + b1 + eigS[r1 * 132 + ncol + 1];
            float a0 = (row0 < sn ? v00 : 0.0f) + (row1 < sn ? v10 : 0.0f);
            float a1 = (row0 < sn ? v01 : 0.0f) + (row1 < sn ? v11 : 0.0f);
            atomicAdd(&colsum[ncol], a0);
            atomicAdd(&colsum[ncol + 1], a1);
        }
    }
    __syncthreads();
    if (tid < 128) atomicAdd(&g_xsum[tid], (double)colsum[tid]);
}

// ============================================================================
// Final: pooled coefficients (computed redundantly per block from g_xsum)
// + Chebyshev synthesis + L2 normalize -> out[S, 5].
// grid = 32, 128 threads.
// ============================================================================
__global__ void __launch_bounds__(128) k_final(const float* __restrict__ eve,
                                               const float* __restrict__ dscW, const float* __restrict__ dscb,
                                               const float* __restrict__ dwvW, const float* __restrict__ dwvb,
                                               const float* __restrict__ dssW, const float* __restrict__ dssb,
                                               const int* __restrict__ lenp, const int* __restrict__ snp,
                                               float* __restrict__ out) {
    __shared__ float sig[104];
    __shared__ float ssum[2];
    __shared__ float cs[NCOE], cw[NCOE], sc[NSCALES];
    const int tid = threadIdx.x;
    const float lenf = (float)(*lenp);
    const float snf  = (float)(*snp);

    if (tid < 104) {
        const float* W; const float* bb; int c; int NCc;
        if (tid < 50)       { W = dscW; bb = dscb; c = tid;       NCc = NCOE; }
        else if (tid < 100) { W = dwvW; bb = dwvb; c = tid - 50;  NCc = NCOE; }
        else                { W = dssW; bb = dssb; c = tid - 100; NCc = NSCALES; }
        double acc = 0.0;
        for (int k = 0; k < HID; k++) acc += g_xsum[k] * (double)W[k * NCc + c];
        float pooled = (float)((acc + (double)(snf * bb[c])) / (double)(lenf + 1e-8f));
        sig[tid] = 1.0f / (1.0f + expf(-pooled));
    }
    __syncthreads();
    if (tid == 0) { float t = 0.f; for (int i = 0;  i < 50;  i++) t += sig[i]; ssum[0] = t; }
    if (tid == 1) { float t = 0.f; for (int i = 50; i < 100; i++) t += sig[i]; ssum[1] = t; }
    __syncthreads();
    if (tid < 50)        cs[tid]       = sig[tid] / (ssum[0] + 1e-8f);
    else if (tid < 100)  cw[tid - 50]  = sig[tid] / (ssum[1] + 1e-8f);
    else if (tid < 104)  sc[tid - 100] = sig[tid] * 5.0f;   // THRE
    __syncthreads();

    for (int s = blockIdx.x * 128 + tid; s < S; s += 32 * 128) {
        const float e = eve[s];
        float vals[5];

        {   // scaling channel: y = e - 1; coefficients on T_1,T_3,...
            float y  = e - 1.0f;
            float te = 1.0f, to = y;
            float acc = cs[0] * (0.5f * (1.0f - to));
#pragma unroll
            for (int c = 1; c < NCOE; c++) {
                te = 2.0f * y * to - te;          // T_{2c}
                to = 2.0f * y * te - to;          // T_{2c+1}
                acc += cs[c] * (0.5f * (1.0f - to));
            }
            vals[0] = acc;
        }

#pragma unroll
        for (int j = 0; j < NSCALES; j++) {       // wavelet channels: T_0,T_2,...
            float f = e * sc[j];
            if (f > 2.0f) f = 0.0f;
            float y  = f - 1.0f;
            float te = 1.0f, to = y;
            float acc = 0.0f;                      // cw[0] * 0.5*(1-T_0) = 0
#pragma unroll
            for (int c = 1; c < NCOE; c++) {
                te = 2.0f * y * to - te;          // T_{2c}
                acc += cw[c] * (0.5f * (1.0f - te));
                to = 2.0f * y * te - to;          // T_{2c+1}
            }
            vals[1 + j] = acc;
        }

        float n2 = 0.0f;
#pragma unroll
        for (int i = 0; i < 5; i++) n2 += vals[i] * vals[i];
        float inv = 1.0f / (sqrtf(n2) + 1e-8f);
#pragma unroll
        for (int i = 0; i < 5; i++) out[s * 5 + i] = vals[i] * inv;
    }
}

// ============================================================================
// launch
// ============================================================================
extern "C" void kernel_launch(void* const* d_in, const int* in_sizes, int n_in,
                              void* d_out, int out_size) {
    const float* eve      = (const float*)d_in[0];
    const int*   lenp     = (const int*)  d_in[1];
    const int*   snp      = (const int*)  d_in[2];
    const float* eig_w_W  = (const float*)d_in[3];
    const float* eig_w_b  = (const float*)d_in[4];
    const float* mha_ln_g = (const float*)d_in[5];
    const float* mha_ln_b = (const float*)d_in[6];
    const float* in_W     = (const float*)d_in[7];
    const float* in_b     = (const float*)d_in[8];
    const float* out_W    = (const float*)d_in[9];
    const float* out_b    = (const float*)d_in[10];
    const float* ffn_ln_g = (const float*)d_in[11];
    const float* ffn_ln_b = (const float*)d_in[12];
    const float* ffn1_W   = (const float*)d_in[13];
    const float* ffn1_b   = (const float*)d_in[14];
    const float* ffn2_W   = (const float*)d_in[15];
    const float* ffn2_b   = (const float*)d_in[16];
    const float* dsc_W    = (const float*)d_in[17];
    const float* dsc_b    = (const float*)d_in[18];
    const float* dwv_W    = (const float*)d_in[19];
    const float* dwv_b    = (const float*)d_in[20];
    const float* dss_W    = (const float*)d_in[21];
    const float* dss_b    = (const float*)d_in[22];
    float* out = (float*)d_out;

    float *p_eig, *p_qkv;
    cudaGetSymbolAddress((void**)&p_eig,  g_eig);
    cudaGetSymbolAddress((void**)&p_qkv,  g_qkv);

    // 1) merged: weight images + xsum zero + g_kv ones + sine encoding
    k_prep0<<<352, 256>>>(in_W, out_W, ffn1_W, ffn2_W, eve, eig_w_W, eig_w_b);
    // 2) qkv: Q -> float g_qkv; K/V -> fp16 g_kv images directly
    k_qkv_mma<<<dim3(128, 3), 256>>>(p_eig, in_b, p_qkv, mha_ln_g, mha_ln_b);
    // 3) attention split-K partials
    k_attn_mma<<<dim3(S / QT, NHEADS, NKC), 256>>>(p_qkv, snp);
    // 4) fused: combine -> out-proj(+resid) -> LN -> ffn1+gelu -> ffn2(+resid) -> colsums
    k_ffn_fused<<<dim3(128), 256>>>(out_b, ffn1_b, ffn2_b, ffn_ln_g, ffn_ln_b, snp);
    // 5) pooled coefficients (per-block) + Chebyshev synthesis + normalize
    k_final<<<32, 128>>>(eve, dsc_W, dsc_b, dwv_W, dwv_b, dss_W, dss_b, lenp, snp, out);
}